// round 7
// baseline (speedup 1.0000x reference)
#include <cuda_runtime.h>

// out[b,t,w,c] = x[b, t+w-9, c], zero-padded in t.  B=32, T=4096, W=19, C=30.
// Identity: out row (b,t) [570 floats] == contiguous x slice starting at
// flat element (b*4096 + t - 9)*30, with pad rows zeroed.
//
// Steady-state DRAM-bound (~6.4 TB/s sustained): 298.6 MB writes + reads.
// This round: TT=128 halves the staging halo re-read (28% -> 14% of input)
// and halves syncs per byte. Emit: 480 threads * 76 iters = 36480 float2 exact.

#define T_DIM   4096
#define C_DIM   30
#define ROW     570             // W*C
#define PAD     9
#define TT      128             // t-rows per block
#define SROWS   (TT + 2*PAD)    // 146
#define SFLOATS (SROWS * C_DIM) // 4380
#define THREADS 480
#define ITERS   76              // TT*ROW/2 / THREADS = 36480/480

__device__ __forceinline__ void stg_cs_v2(float2* p, float2 v) {
    asm volatile("st.global.cs.v2.f32 [%0], {%1,%2};"
                 :: "l"(p), "f"(v.x), "f"(v.y) : "memory");
}

__global__ __launch_bounds__(THREADS)
void overlap_window_smem_kernel(const float* __restrict__ x,
                                float2* __restrict__ out2) {
    __shared__ float s[SFLOATS];

    const int tile = blockIdx.x;            // 0 .. 1023
    const int tpb  = T_DIM / TT;            // 32 tiles per batch
    const int b    = tile / tpb;
    const int t0   = (tile - b * tpb) * TT;
    const int tid  = threadIdx.x;

    // ---- stage x[(b*4096 + t0 - 9)*30 ... +4380) into smem, zeroing pad ----
    const int lo = (t0 == 0) ? (PAD * C_DIM) : 0;
    const int hi_raw = (T_DIM - t0 + PAD) * C_DIM;
    const int hi = hi_raw < SFLOATS ? hi_raw : SFLOATS;
    const int gbase = (b * T_DIM + t0 - PAD) * C_DIM;  // even
    const float2* __restrict__ x2 = (const float2*)x;
    float2* __restrict__ s2 = (float2*)s;

    #pragma unroll
    for (int k = 0; k < (SFLOATS / 2 + THREADS - 1) / THREADS; k++) {
        int idx2 = tid + k * THREADS;
        if (idx2 < SFLOATS / 2) {
            int i = idx2 * 2;
            float2 v = make_float2(0.0f, 0.0f);
            if (i >= lo && i < hi) {
                v = __ldg(&x2[(gbase >> 1) + idx2]);
            }
            s2[idx2] = v;
        }
    }
    __syncthreads();

    // ---- emit 36480 float2s; float2 index q = tid + k*480, element e = 2q ----
    // output row r = e/570, rem = e - 570r (even); smem source = r*30 + rem.
    // e advances 960 per iter: rem += 390 (mod 570), r += 1 or 2.
    float2* __restrict__ out_tile = out2 + ((size_t)(b * T_DIM + t0) * ROW) / 2;

    int e   = tid * 2;                  // 0..958
    int r   = (e >= ROW) ? 1 : 0;
    int rem = e - r * ROW;

    #pragma unroll
    for (int k = 0; k < ITERS; k++) {
        int src = r * C_DIM + rem;      // even -> 8B aligned
        float2 v = *(const float2*)&s[src];
        stg_cs_v2(&out_tile[tid + k * THREADS], v);

        rem += 960 - ROW;               // += 390
        r   += 1;
        if (rem >= ROW) { rem -= ROW; r += 1; }
    }
}

extern "C" void kernel_launch(void* const* d_in, const int* in_sizes, int n_in,
                              void* d_out, int out_size) {
    const float* x = (const float*)d_in[0];
    float2* out2 = (float2*)d_out;
    const int blocks = 32 * (T_DIM / TT);   // 1024
    overlap_window_smem_kernel<<<blocks, THREADS>>>(x, out2);
}

// round 8
// speedup vs baseline: 1.0481x; 1.0481x over previous
#include <cuda_runtime.h>

// out[b,t,w,c] = x[b, t+w-9, c], zero-padded in t.  B=32, T=4096, W=19, C=30.
// Identity: out row (b,t) [570 floats] == contiguous x slice starting at
// flat element (b*4096 + t - 9)*30, with out-of-range t zeroed.
//
// No-smem variant: block owns TT=64 contiguous t-rows (36480 floats out,
// 9.8 KB source footprint read 19x -> L1-resident after first touch).
// Emit float2: 480 threads * 38 iters = 18240 exact, no bounds checks on q.
// Validity: element pair (rem, rem+1) shares st = t0 + r - 9 + widx, where
// widx = rem/30 is maintained incrementally (exact: 390 = 13*30, 570 = 19*30).

#define T_DIM   4096
#define C_DIM   30
#define ROW     570             // W*C
#define PAD     9
#define TT      64              // t-rows per block
#define THREADS 480
#define ITERS   38              // TT*ROW/2 / THREADS = 18240/480

__device__ __forceinline__ void stg_cs_v2(float2* p, float2 v) {
    asm volatile("st.global.cs.v2.f32 [%0], {%1,%2};"
                 :: "l"(p), "f"(v.x), "f"(v.y) : "memory");
}

__global__ __launch_bounds__(THREADS)
void overlap_window_direct_kernel(const float* __restrict__ x,
                                  float2* __restrict__ out2) {
    const int tile = blockIdx.x;            // 0 .. 2047
    const int tpb  = T_DIM / TT;            // 64 tiles per batch
    const int b    = tile / tpb;
    const int t0   = (tile - b * tpb) * TT;
    const int tid  = threadIdx.x;

    // per-thread initial decomposition of e = tid*2 (0..958)
    int e    = tid * 2;
    int r    = (e >= ROW) ? 1 : 0;
    int rem  = e - r * ROW;                 // even, 0..568
    int widx = rem / C_DIM;                 // 0..18 (one divide, setup only)

    // source float2 pointer for (r, rem): x flat ((b*4096 + t0 + r - 9)*30 + rem)/2
    const float2* __restrict__ x2 = (const float2*)x;
    const int src_base2 = ((b * T_DIM + t0 - PAD) * C_DIM) >> 1;  // even/2

    float2* __restrict__ out_tile = out2 + ((size_t)(b * T_DIM + t0) * ROW) / 2;

    #pragma unroll
    for (int k = 0; k < ITERS; k++) {
        int st = t0 + r - PAD + widx;       // source timestep
        float2 v = make_float2(0.0f, 0.0f);
        if ((unsigned)st < (unsigned)T_DIM) {
            v = __ldg(&x2[src_base2 + ((r * C_DIM + rem) >> 1)]);
        }
        stg_cs_v2(&out_tile[tid + k * THREADS], v);

        // advance e += 960: rem += 390, widx += 13, r += 1; wrap at 570
        rem  += 390;
        widx += 13;
        r    += 1;
        if (rem >= ROW) { rem -= ROW; widx -= 19; r += 1; }
    }
}

extern "C" void kernel_launch(void* const* d_in, const int* in_sizes, int n_in,
                              void* d_out, int out_size) {
    const float* x = (const float*)d_in[0];
    float2* out2 = (float2*)d_out;
    const int blocks = 32 * (T_DIM / TT);   // 2048
    overlap_window_direct_kernel<<<blocks, THREADS>>>(x, out2);
}